// round 10
// baseline (speedup 1.0000x reference)
#include <cuda_runtime.h>
#include <cuda_bf16.h>
#include <cstdint>

#define NN 40000
#define EE 640000
#define CC 128
#define SCAN_BLK 1024

// ---------------- scratch (static device globals; no allocation allowed) ----
__device__ float g_h[NN * CC];        // transformed node features
__device__ float g_asrc[NN];
__device__ float g_adst[NN];
__device__ float g_ae[EE];            // per-edge attention logit (edge term)
__device__ int   g_src[EE];
__device__ int   g_dst[EE];
__device__ int   g_count[NN];         // per-dst degree histogram
__device__ int   g_rowptr[NN + 1];    // CSR row pointers (by dst)
__device__ int   g_wofs[NN];          // scatter cursors (copy of rowptr)
__device__ int   g_blksum[64];        // scan phase-1 block totals
__device__ int2  g_sedge[EE];         // dst-sorted {src, bits(ex)} records

// ---------------- packed f32x2 helpers --------------------------------------
__device__ __forceinline__ unsigned long long f32x2_fma(unsigned long long a,
                                                        unsigned long long b,
                                                        unsigned long long c) {
    unsigned long long d;
    asm("fma.rn.f32x2 %0, %1, %2, %3;" : "=l"(d) : "l"(a), "l"(b), "l"(c));
    return d;
}
__device__ __forceinline__ unsigned long long f32_dup(float x) {
    unsigned long long d;
    asm("mov.b64 %0, {%1, %1};" : "=l"(d) : "f"(x));
    return d;
}
__device__ __forceinline__ void f32x2_unpack(unsigned long long v, float& lo, float& hi) {
    asm("mov.b64 {%0, %1}, %2;" : "=f"(lo), "=f"(hi) : "l"(v));
}

// ---------------- K1: dtype-robust edge_index unpack + dst histogram --------
__global__ void convert_idx_kernel(const int* __restrict__ ei32, int E, int N) {
    __shared__ int is64_s;
    if (threadIdx.x == 0) {
        int orv = 0;
        #pragma unroll 8
        for (int i = 1; i < 256; i += 2) orv |= ei32[i];
        is64_s = (orv == 0) ? 1 : 0;
    }
    __syncthreads();
    const bool is64 = (is64_s != 0);
    int i = blockIdx.x * blockDim.x + threadIdx.x;
    int stride = gridDim.x * blockDim.x;
    for (int e = i; e < E; e += stride) {
        int s, d;
        if (is64) {
            s = ei32[2 * (size_t)e];
            d = ei32[2 * ((size_t)E + e)];
        } else {
            s = ei32[e];
            d = ei32[(size_t)E + e];
        }
        s = min(max(s, 0), N - 1);
        d = min(max(d, 0), N - 1);
        g_src[e] = s;
        g_dst[e] = d;
        atomicAdd(&g_count[d], 1);
    }
}

// ---------------- K2a/b/c: 3-phase parallel exclusive scan ------------------
__device__ __forceinline__ int block_excl_scan_1024(int v, int* warp_sums) {
    int lane = threadIdx.x & 31, wid = threadIdx.x >> 5;
    int x = v;
    #pragma unroll
    for (int off = 1; off < 32; off <<= 1) {
        int y = __shfl_up_sync(0xffffffffu, x, off);
        if (lane >= off) x += y;
    }
    if (lane == 31) warp_sums[wid] = x;
    __syncthreads();
    if (wid == 0) {
        int s = warp_sums[lane];
        #pragma unroll
        for (int off = 1; off < 32; off <<= 1) {
            int y = __shfl_up_sync(0xffffffffu, s, off);
            if (lane >= off) s += y;
        }
        warp_sums[lane] = s;
    }
    __syncthreads();
    int warp_prefix = (wid == 0) ? 0 : warp_sums[wid - 1];
    return warp_prefix + x - v;   // exclusive
}

__global__ void scan_phase1(int N) {
    __shared__ int warp_sums[32];
    int i = blockIdx.x * SCAN_BLK + threadIdx.x;
    int v = (i < N) ? g_count[i] : 0;
    int excl = block_excl_scan_1024(v, warp_sums);
    if (i < N) g_rowptr[i] = excl;
    if (threadIdx.x == SCAN_BLK - 1) g_blksum[blockIdx.x] = excl + v;
}
__global__ void scan_phase2(int nblk) {
    __shared__ int warp_sums[32];
    int v = (threadIdx.x < nblk) ? g_blksum[threadIdx.x] : 0;
    int excl = block_excl_scan_1024(v, warp_sums);
    if (threadIdx.x < nblk) g_blksum[threadIdx.x] = excl;
}
__global__ void scan_phase3(int N, int E) {
    int i = blockIdx.x * SCAN_BLK + threadIdx.x;
    if (i < N) {
        int r = g_rowptr[i] + g_blksum[blockIdx.x];
        g_rowptr[i] = r;
        g_wofs[i] = r;
    }
    if (i == 0) g_rowptr[N] = E;
}

// ---------------- K3: h = x @ W  (+ fused a_src, a_dst) ---------------------
// 128x128 block tile, 256 threads, 8 rows x 4 col-pairs per thread.
__global__ __launch_bounds__(256, 2) void gemm_h_kernel(
    const float* __restrict__ x, const float* __restrict__ W,
    const float* __restrict__ att_src, const float* __restrict__ att_dst,
    int N) {
    extern __shared__ float2 Wp[];                      // [128][64] pairs = 64 KB
    const unsigned long long* Wd = (const unsigned long long*)Wp;

    int tid = threadIdx.x;
    int row0 = blockIdx.x * 128;

    for (int idx = tid; idx < 2048; idx += 256) {
        int k = idx >> 4, p4 = (idx & 15) * 4;
        float4 a = *(const float4*)(W + k * 128 + p4);
        float4 b = *(const float4*)(W + k * 128 + p4 + 64);
        Wp[k * 64 + p4 + 0] = make_float2(a.x, b.x);
        Wp[k * 64 + p4 + 1] = make_float2(a.y, b.y);
        Wp[k * 64 + p4 + 2] = make_float2(a.z, b.z);
        Wp[k * 64 + p4 + 3] = make_float2(a.w, b.w);
    }
    __syncthreads();

    int tx = tid & 15, ty = tid >> 4;

    const float* xr[8];
    #pragma unroll
    for (int i = 0; i < 8; i++) {
        int row = min(row0 + ty * 8 + i, N - 1);
        xr[i] = x + (size_t)row * 128;
    }

    unsigned long long acc[8][4];
    #pragma unroll
    for (int i = 0; i < 8; i++)
        #pragma unroll
        for (int j = 0; j < 4; j++) acc[i][j] = 0ull;

    #pragma unroll 2
    for (int k0 = 0; k0 < 128; k0 += 2) {
        float2 xv[8];
        #pragma unroll
        for (int i = 0; i < 8; i++)
            xv[i] = *(const float2*)(xr[i] + k0);
        #pragma unroll
        for (int kk = 0; kk < 2; kk++) {
            unsigned long long w01[4];
            #pragma unroll
            for (int j = 0; j < 4; j++)
                w01[j] = Wd[(k0 + kk) * 64 + tx + 16 * j];
            #pragma unroll
            for (int i = 0; i < 8; i++) {
                unsigned long long ax = f32_dup(kk ? xv[i].y : xv[i].x);
                #pragma unroll
                for (int j = 0; j < 4; j++)
                    acc[i][j] = f32x2_fma(ax, w01[j], acc[i][j]);
            }
        }
    }

    float as_l[4], as_h[4], ad_l[4], ad_h[4];
    #pragma unroll
    for (int j = 0; j < 4; j++) {
        int c0 = tx + 16 * j;
        as_l[j] = att_src[c0];      as_h[j] = att_src[c0 + 64];
        ad_l[j] = att_dst[c0];      ad_h[j] = att_dst[c0 + 64];
    }
    #pragma unroll
    for (int i = 0; i < 8; i++) {
        int row = row0 + ty * 8 + i;
        float psrc = 0.f, pdst = 0.f;
        #pragma unroll
        for (int j = 0; j < 4; j++) {
            float lo, hi;
            f32x2_unpack(acc[i][j], lo, hi);
            int c0 = tx + 16 * j;
            if (row < N) {
                g_h[(size_t)row * 128 + c0]      = lo;
                g_h[(size_t)row * 128 + c0 + 64] = hi;
            }
            psrc += lo * as_l[j] + hi * as_h[j];
            pdst += lo * ad_l[j] + hi * ad_h[j];
        }
        #pragma unroll
        for (int off = 8; off > 0; off >>= 1) {
            psrc += __shfl_down_sync(0xffffffffu, psrc, off, 16);
            pdst += __shfl_down_sync(0xffffffffu, pdst, off, 16);
        }
        if (tx == 0 && row < N) {
            g_asrc[row] = psrc;
            g_adst[row] = pdst;
        }
    }
}

// ---------------- K4: g_ae[e] = edge_attr[e] . (W_edge @ att_edge) ----------
// Runs on the prep stream AFTER the scan (overlaps only the gemm's tail).
__global__ __launch_bounds__(256) void ae_kernel(
    const float* __restrict__ edge_attr,
    const float* __restrict__ W_edge,
    const float* __restrict__ att_edge, int E) {
    __shared__ float wv_s[32];
    __shared__ float part_s[8][32];
    __shared__ float ae_s[8][32];
    int tid = threadIdx.x, lane = tid & 31, w = tid >> 5;

    // cooperative wv: thread (w, lane) sums 16 elems of row `lane`
    {
        float p = 0.f;
        #pragma unroll
        for (int c = 0; c < 16; c++) {
            int col = w * 16 + c;
            p += W_edge[lane * 128 + col] * att_edge[col];
        }
        part_s[w][lane] = p;
        __syncthreads();
        if (tid < 32) {
            float s = 0.f;
            #pragma unroll
            for (int q = 0; q < 8; q++) s += part_s[q][tid];
            wv_s[tid] = s;
        }
        __syncthreads();
    }

    int ebase = (blockIdx.x * 8 + w) * 32;
    if (ebase >= E) return;

    if (ebase + 32 <= E) {
        const float4* base = (const float4*)(edge_attr + (size_t)ebase * 32);
        float w0 = wv_s[(lane & 7) * 4 + 0], w1 = wv_s[(lane & 7) * 4 + 1];
        float w2 = wv_s[(lane & 7) * 4 + 2], w3 = wv_s[(lane & 7) * 4 + 3];
        #pragma unroll
        for (int j = 0; j < 8; j++) {
            float4 v = base[j * 32 + lane];
            float p = v.x * w0 + v.y * w1 + v.z * w2 + v.w * w3;
            p += __shfl_down_sync(0xffffffffu, p, 4, 8);
            p += __shfl_down_sync(0xffffffffu, p, 2, 8);
            p += __shfl_down_sync(0xffffffffu, p, 1, 8);
            if ((lane & 7) == 0) ae_s[w][j * 4 + (lane >> 3)] = p;
        }
        __syncwarp();
        g_ae[ebase + lane] = ae_s[w][lane];
    } else {
        int e = ebase + lane;
        if (e < E) {
            const float4* ea = (const float4*)(edge_attr + (size_t)e * 32);
            float ae = 0.f;
            #pragma unroll
            for (int j = 0; j < 8; j++) {
                float4 v = ea[j];
                ae += v.x * wv_s[4 * j] + v.y * wv_s[4 * j + 1]
                    + v.z * wv_s[4 * j + 2] + v.w * wv_s[4 * j + 3];
            }
            g_ae[e] = ae;
        }
    }
}

// ---------------- K5: alpha -> exp, scatter into dst-sorted CSR (light) -----
__global__ __launch_bounds__(256) void edge_scatter(int E) {
    int e = blockIdx.x * blockDim.x + threadIdx.x;
    if (e >= E) return;
    int src = g_src[e];
    int dst = g_dst[e];
    float al = g_asrc[src] + g_adst[dst] + g_ae[e];
    al = al > 0.f ? al : 0.2f * al;          // leaky_relu(0.2)
    float ex = __expf(al);                   // alpha range small; no max-shift needed
    int pos = atomicAdd(&g_wofs[dst], 1);
    g_sedge[pos] = make_int2(src, __float_as_int(ex));
}

// ---------------- K6: warp-per-dst CSR reduction (denom fused) --------------
// (R6-proven inner loop, no prefetch rotation)
__global__ __launch_bounds__(256) void aggregate_kernel(
    const float* __restrict__ bias, float* __restrict__ out, int N) {
    int warp = (blockIdx.x * blockDim.x + threadIdx.x) >> 5;
    int lane = threadIdx.x & 31;
    if (warp >= N) return;
    int beg = g_rowptr[warp];
    int end = g_rowptr[warp + 1];

    float4 acc = make_float4(0.f, 0.f, 0.f, 0.f);
    float denom = 0.f;
    int e = beg;
    for (; e + 4 <= end; e += 4) {
        int2 p0 = g_sedge[e],     p1 = g_sedge[e + 1];
        int2 p2 = g_sedge[e + 2], p3 = g_sedge[e + 3];
        float4 h0 = *(const float4*)(g_h + (size_t)p0.x * 128 + lane * 4);
        float4 h1 = *(const float4*)(g_h + (size_t)p1.x * 128 + lane * 4);
        float4 h2 = *(const float4*)(g_h + (size_t)p2.x * 128 + lane * 4);
        float4 h3 = *(const float4*)(g_h + (size_t)p3.x * 128 + lane * 4);
        float e0 = __int_as_float(p0.y), e1 = __int_as_float(p1.y);
        float e2 = __int_as_float(p2.y), e3 = __int_as_float(p3.y);
        acc.x = fmaf(e0, h0.x, acc.x); acc.y = fmaf(e0, h0.y, acc.y);
        acc.z = fmaf(e0, h0.z, acc.z); acc.w = fmaf(e0, h0.w, acc.w);
        acc.x = fmaf(e1, h1.x, acc.x); acc.y = fmaf(e1, h1.y, acc.y);
        acc.z = fmaf(e1, h1.z, acc.z); acc.w = fmaf(e1, h1.w, acc.w);
        acc.x = fmaf(e2, h2.x, acc.x); acc.y = fmaf(e2, h2.y, acc.y);
        acc.z = fmaf(e2, h2.z, acc.z); acc.w = fmaf(e2, h2.w, acc.w);
        acc.x = fmaf(e3, h3.x, acc.x); acc.y = fmaf(e3, h3.y, acc.y);
        acc.z = fmaf(e3, h3.z, acc.z); acc.w = fmaf(e3, h3.w, acc.w);
        denom += (e0 + e1) + (e2 + e3);
    }
    for (; e < end; e++) {
        int2 p0 = g_sedge[e];
        float e0 = __int_as_float(p0.y);
        float4 h0 = *(const float4*)(g_h + (size_t)p0.x * 128 + lane * 4);
        acc.x = fmaf(e0, h0.x, acc.x); acc.y = fmaf(e0, h0.y, acc.y);
        acc.z = fmaf(e0, h0.z, acc.z); acc.w = fmaf(e0, h0.w, acc.w);
        denom += e0;
    }
    float wgt = __fdividef(1.0f, denom + 1e-16f);
    float4 b = *(const float4*)(bias + lane * 4);
    float4 o;
    o.x = fmaf(acc.x, wgt, b.x);
    o.y = fmaf(acc.y, wgt, b.y);
    o.z = fmaf(acc.z, wgt, b.z);
    o.w = fmaf(acc.w, wgt, b.w);
    *(float4*)(out + (size_t)warp * 128 + lane * 4) = o;
}

// ---------------- launch -----------------------------------------------------
extern "C" void kernel_launch(void* const* d_in, const int* in_sizes, int n_in,
                              void* d_out, int out_size) {
    const float* x         = (const float*)d_in[0];
    const int*   ei32      = (const int*)d_in[1];
    const float* edge_attr = (const float*)d_in[2];
    const float* W         = (const float*)d_in[3];
    const float* W_edge    = (const float*)d_in[4];
    const float* att_src   = (const float*)d_in[5];
    const float* att_dst   = (const float*)d_in[6];
    const float* att_edge  = (const float*)d_in[7];
    const float* bias      = (const float*)d_in[8];
    float* out = (float*)d_out;

    int N = in_sizes[0] / 128;
    int E = in_sizes[1] / 2;
    int nblk = (N + SCAN_BLK - 1) / SCAN_BLK;

    // One-time resources, created on the first (non-capture) correctness call.
    static bool s_init = false;
    static cudaStream_t s_gemm;
    static cudaEvent_t s_evFork, s_evJoin;
    static void* s_countPtr = nullptr;
    if (!s_init) {
        cudaStreamCreateWithFlags(&s_gemm, cudaStreamNonBlocking);
        cudaEventCreateWithFlags(&s_evFork, cudaEventDisableTiming);
        cudaEventCreateWithFlags(&s_evJoin, cudaEventDisableTiming);
        cudaGetSymbolAddress(&s_countPtr, g_count);
        const int GEMM_SMEM = 128 * 64 * (int)sizeof(float2);
        cudaFuncSetAttribute(gemm_h_kernel, cudaFuncAttributeMaxDynamicSharedMemorySize, GEMM_SMEM);
        s_init = true;
    }
    const int GEMM_SMEM = 128 * 64 * (int)sizeof(float2);   // 64 KB

    // fork: gemm branch runs concurrently with the prep branch
    cudaEventRecord(s_evFork, 0);
    cudaStreamWaitEvent(s_gemm, s_evFork, 0);
    gemm_h_kernel<<<(N + 127) / 128, 256, GEMM_SMEM, s_gemm>>>(x, W, att_src, att_dst, N);
    cudaEventRecord(s_evJoin, s_gemm);

    // prep branch (base stream): index prep, then edge-attr dot (overlaps gemm tail)
    cudaMemsetAsync(s_countPtr, 0, (size_t)N * sizeof(int), 0);
    convert_idx_kernel<<<1024, 256>>>(ei32, E, N);
    scan_phase1<<<nblk, SCAN_BLK>>>(N);
    scan_phase2<<<1, SCAN_BLK>>>(nblk);
    scan_phase3<<<nblk, SCAN_BLK>>>(N, E);
    ae_kernel<<<(E + 255) / 256, 256>>>(edge_attr, W_edge, att_edge, E);

    // join: scatter needs gemm (a_src/a_dst) + prep (wofs, ae)
    cudaStreamWaitEvent(0, s_evJoin, 0);
    edge_scatter<<<(E + 255) / 256, 256>>>(E);
    aggregate_kernel<<<(N * 32 + 255) / 256, 256>>>(bias, out, N);
}

// round 11
// speedup vs baseline: 1.3294x; 1.3294x over previous
#include <cuda_runtime.h>
#include <cuda_bf16.h>
#include <cuda_fp16.h>
#include <cstdint>

#define NN 40000
#define EE 640000
#define CC 128
#define SCAN_BLK 1024

// ---------------- scratch (static device globals; no allocation allowed) ----
__device__ __half g_hh[NN * CC];      // transformed node features (fp16 storage)
__device__ float g_asrc[NN];
__device__ float g_adst[NN];
__device__ float g_wv[32];            // W_edge @ att_edge (collapsed edge GEMM)
__device__ int   g_src[EE];
__device__ int   g_dst[EE];
__device__ int   g_count[NN];         // per-dst degree histogram
__device__ int   g_rowptr[NN + 1];    // CSR row pointers (by dst)
__device__ int   g_wofs[NN];          // scatter cursors (copy of rowptr)
__device__ int   g_blksum[64];        // scan phase-1 block totals
__device__ int2  g_sedge[EE];         // dst-sorted {src, bits(ex)} records

// ---------------- packed f32x2 helpers --------------------------------------
__device__ __forceinline__ unsigned long long f32x2_fma(unsigned long long a,
                                                        unsigned long long b,
                                                        unsigned long long c) {
    unsigned long long d;
    asm("fma.rn.f32x2 %0, %1, %2, %3;" : "=l"(d) : "l"(a), "l"(b), "l"(c));
    return d;
}
__device__ __forceinline__ unsigned long long f32_dup(float x) {
    unsigned long long d;
    asm("mov.b64 %0, {%1, %1};" : "=l"(d) : "f"(x));
    return d;
}
__device__ __forceinline__ void f32x2_unpack(unsigned long long v, float& lo, float& hi) {
    asm("mov.b64 {%0, %1}, %2;" : "=f"(lo), "=f"(hi) : "l"(v));
}

// fp16 gather helper: 4 consecutive halves at (row, lane*4) as float4 (one LDG.64)
__device__ __forceinline__ float4 load_h4(int row, int lane) {
    uint2 u = *(const uint2*)(g_hh + (size_t)row * 128 + lane * 4);
    __half2 a = *reinterpret_cast<const __half2*>(&u.x);
    __half2 b = *reinterpret_cast<const __half2*>(&u.y);
    float2 fa = __half22float2(a), fb = __half22float2(b);
    return make_float4(fa.x, fa.y, fb.x, fb.y);
}

// ---------------- K0: zero counters, wv = W_edge @ att_edge -----------------
__global__ void init_kernel(const float* __restrict__ W_edge,
                            const float* __restrict__ att_edge, int N) {
    int i = blockIdx.x * blockDim.x + threadIdx.x;
    if (blockIdx.x == 0 && threadIdx.x < 32) {
        float s = 0.f;
        #pragma unroll 4
        for (int c = 0; c < 128; c++) s += W_edge[threadIdx.x * 128 + c] * att_edge[c];
        g_wv[threadIdx.x] = s;
    }
    int stride = gridDim.x * blockDim.x;
    for (int idx = i; idx < N; idx += stride) g_count[idx] = 0;
}

// ---------------- K1: dtype-robust edge_index unpack + dst histogram --------
__global__ void convert_idx_kernel(const int* __restrict__ ei32, int E, int N) {
    __shared__ int is64_s;
    if (threadIdx.x == 0) {
        int orv = 0;
        #pragma unroll 8
        for (int i = 1; i < 256; i += 2) orv |= ei32[i];
        is64_s = (orv == 0) ? 1 : 0;
    }
    __syncthreads();
    const bool is64 = (is64_s != 0);
    int i = blockIdx.x * blockDim.x + threadIdx.x;
    int stride = gridDim.x * blockDim.x;
    for (int e = i; e < E; e += stride) {
        int s, d;
        if (is64) {
            s = ei32[2 * (size_t)e];
            d = ei32[2 * ((size_t)E + e)];
        } else {
            s = ei32[e];
            d = ei32[(size_t)E + e];
        }
        s = min(max(s, 0), N - 1);
        d = min(max(d, 0), N - 1);
        g_src[e] = s;
        g_dst[e] = d;
        atomicAdd(&g_count[d], 1);
    }
}

// ---------------- K2a/b/c: 3-phase parallel exclusive scan ------------------
__device__ __forceinline__ int block_excl_scan_1024(int v, int* warp_sums) {
    int lane = threadIdx.x & 31, wid = threadIdx.x >> 5;
    int x = v;
    #pragma unroll
    for (int off = 1; off < 32; off <<= 1) {
        int y = __shfl_up_sync(0xffffffffu, x, off);
        if (lane >= off) x += y;
    }
    if (lane == 31) warp_sums[wid] = x;
    __syncthreads();
    if (wid == 0) {
        int s = warp_sums[lane];
        #pragma unroll
        for (int off = 1; off < 32; off <<= 1) {
            int y = __shfl_up_sync(0xffffffffu, s, off);
            if (lane >= off) s += y;
        }
        warp_sums[lane] = s;
    }
    __syncthreads();
    int warp_prefix = (wid == 0) ? 0 : warp_sums[wid - 1];
    return warp_prefix + x - v;   // exclusive
}

__global__ void scan_phase1(int N) {
    __shared__ int warp_sums[32];
    int i = blockIdx.x * SCAN_BLK + threadIdx.x;
    int v = (i < N) ? g_count[i] : 0;
    int excl = block_excl_scan_1024(v, warp_sums);
    if (i < N) g_rowptr[i] = excl;
    if (threadIdx.x == SCAN_BLK - 1) g_blksum[blockIdx.x] = excl + v;
}
__global__ void scan_phase2(int nblk) {
    __shared__ int warp_sums[32];
    int v = (threadIdx.x < nblk) ? g_blksum[threadIdx.x] : 0;
    int excl = block_excl_scan_1024(v, warp_sums);
    if (threadIdx.x < nblk) g_blksum[threadIdx.x] = excl;
}
__global__ void scan_phase3(int N, int E) {
    int i = blockIdx.x * SCAN_BLK + threadIdx.x;
    if (i < N) {
        int r = g_rowptr[i] + g_blksum[blockIdx.x];
        g_rowptr[i] = r;
        g_wofs[i] = r;
    }
    if (i == 0) g_rowptr[N] = E;
}

// ---------------- K3: h = x @ W  (+ fused a_src, a_dst) ---------------------
// 128x128 block tile, 256 threads, 8 rows x 4 col-pairs per thread.
// h stored as fp16 (halves aggregate gather traffic); dots kept fp32.
__global__ __launch_bounds__(256, 2) void gemm_h_kernel(
    const float* __restrict__ x, const float* __restrict__ W,
    const float* __restrict__ att_src, const float* __restrict__ att_dst,
    int N) {
    extern __shared__ float2 Wp[];                      // [128][64] pairs = 64 KB
    const unsigned long long* Wd = (const unsigned long long*)Wp;

    int tid = threadIdx.x;
    int row0 = blockIdx.x * 128;

    for (int idx = tid; idx < 2048; idx += 256) {
        int k = idx >> 4, p4 = (idx & 15) * 4;
        float4 a = *(const float4*)(W + k * 128 + p4);
        float4 b = *(const float4*)(W + k * 128 + p4 + 64);
        Wp[k * 64 + p4 + 0] = make_float2(a.x, b.x);
        Wp[k * 64 + p4 + 1] = make_float2(a.y, b.y);
        Wp[k * 64 + p4 + 2] = make_float2(a.z, b.z);
        Wp[k * 64 + p4 + 3] = make_float2(a.w, b.w);
    }
    __syncthreads();

    int tx = tid & 15, ty = tid >> 4;

    const float* xr[8];
    #pragma unroll
    for (int i = 0; i < 8; i++) {
        int row = min(row0 + ty * 8 + i, N - 1);
        xr[i] = x + (size_t)row * 128;
    }

    unsigned long long acc[8][4];
    #pragma unroll
    for (int i = 0; i < 8; i++)
        #pragma unroll
        for (int j = 0; j < 4; j++) acc[i][j] = 0ull;

    #pragma unroll 2
    for (int k0 = 0; k0 < 128; k0 += 2) {
        float2 xv[8];
        #pragma unroll
        for (int i = 0; i < 8; i++)
            xv[i] = *(const float2*)(xr[i] + k0);
        #pragma unroll
        for (int kk = 0; kk < 2; kk++) {
            unsigned long long w01[4];
            #pragma unroll
            for (int j = 0; j < 4; j++)
                w01[j] = Wd[(k0 + kk) * 64 + tx + 16 * j];
            #pragma unroll
            for (int i = 0; i < 8; i++) {
                unsigned long long ax = f32_dup(kk ? xv[i].y : xv[i].x);
                #pragma unroll
                for (int j = 0; j < 4; j++)
                    acc[i][j] = f32x2_fma(ax, w01[j], acc[i][j]);
            }
        }
    }

    float as_l[4], as_h[4], ad_l[4], ad_h[4];
    #pragma unroll
    for (int j = 0; j < 4; j++) {
        int c0 = tx + 16 * j;
        as_l[j] = att_src[c0];      as_h[j] = att_src[c0 + 64];
        ad_l[j] = att_dst[c0];      ad_h[j] = att_dst[c0 + 64];
    }
    #pragma unroll
    for (int i = 0; i < 8; i++) {
        int row = row0 + ty * 8 + i;
        float psrc = 0.f, pdst = 0.f;
        #pragma unroll
        for (int j = 0; j < 4; j++) {
            float lo, hi;
            f32x2_unpack(acc[i][j], lo, hi);
            int c0 = tx + 16 * j;
            if (row < N) {
                g_hh[(size_t)row * 128 + c0]      = __float2half_rn(lo);
                g_hh[(size_t)row * 128 + c0 + 64] = __float2half_rn(hi);
            }
            psrc += lo * as_l[j] + hi * as_h[j];
            pdst += lo * ad_l[j] + hi * ad_h[j];
        }
        #pragma unroll
        for (int off = 8; off > 0; off >>= 1) {
            psrc += __shfl_down_sync(0xffffffffu, psrc, off, 16);
            pdst += __shfl_down_sync(0xffffffffu, pdst, off, 16);
        }
        if (tx == 0 && row < N) {
            g_asrc[row] = psrc;
            g_adst[row] = pdst;
        }
    }
}

// ---------------- K4: per-edge alpha -> exp, scatter into dst-sorted CSR ----
// (R6-proven monolithic version: coalesced edge_attr dot + scatter in one pass)
__global__ __launch_bounds__(256) void edge_pass1(
    const float* __restrict__ edge_attr, int E) {
    __shared__ float wv_s[32];
    __shared__ float ae_s[8][32];
    int tid = threadIdx.x, lane = tid & 31, w = tid >> 5;
    if (tid < 32) wv_s[tid] = g_wv[tid];
    __syncthreads();

    int ebase = (blockIdx.x * 8 + w) * 32;
    if (ebase >= E) return;

    float ae;
    if (ebase + 32 <= E) {
        const float4* base = (const float4*)(edge_attr + (size_t)ebase * 32);
        float w0 = wv_s[(lane & 7) * 4 + 0], w1 = wv_s[(lane & 7) * 4 + 1];
        float w2 = wv_s[(lane & 7) * 4 + 2], w3 = wv_s[(lane & 7) * 4 + 3];
        #pragma unroll
        for (int j = 0; j < 8; j++) {
            float4 v = base[j * 32 + lane];
            float p = v.x * w0 + v.y * w1 + v.z * w2 + v.w * w3;
            p += __shfl_down_sync(0xffffffffu, p, 4, 8);
            p += __shfl_down_sync(0xffffffffu, p, 2, 8);
            p += __shfl_down_sync(0xffffffffu, p, 1, 8);
            if ((lane & 7) == 0) ae_s[w][j * 4 + (lane >> 3)] = p;
        }
        __syncwarp();
        ae = ae_s[w][lane];
    } else {
        ae = 0.f;
        int e = ebase + lane;
        if (e < E) {
            const float4* ea = (const float4*)(edge_attr + (size_t)e * 32);
            #pragma unroll
            for (int j = 0; j < 8; j++) {
                float4 v = ea[j];
                ae += v.x * wv_s[4 * j] + v.y * wv_s[4 * j + 1]
                    + v.z * wv_s[4 * j + 2] + v.w * wv_s[4 * j + 3];
            }
        }
    }

    int e = ebase + lane;
    if (e >= E) return;
    int src = g_src[e];
    int dst = g_dst[e];
    float al = g_asrc[src] + g_adst[dst] + ae;
    al = al > 0.f ? al : 0.2f * al;          // leaky_relu(0.2)
    float ex = __expf(al);
    int pos = atomicAdd(&g_wofs[dst], 1);
    g_sedge[pos] = make_int2(src, __float_as_int(ex));
}

// ---------------- K5: warp-per-dst CSR reduction (denom fused, fp16 gather) -
__global__ __launch_bounds__(256) void aggregate_kernel(
    const float* __restrict__ bias, float* __restrict__ out, int N) {
    int warp = (blockIdx.x * blockDim.x + threadIdx.x) >> 5;
    int lane = threadIdx.x & 31;
    if (warp >= N) return;
    int beg = g_rowptr[warp];
    int end = g_rowptr[warp + 1];

    float4 acc = make_float4(0.f, 0.f, 0.f, 0.f);
    float denom = 0.f;
    int e = beg;
    for (; e + 4 <= end; e += 4) {
        int2 p0 = g_sedge[e],     p1 = g_sedge[e + 1];
        int2 p2 = g_sedge[e + 2], p3 = g_sedge[e + 3];
        float4 h0 = load_h4(p0.x, lane);
        float4 h1 = load_h4(p1.x, lane);
        float4 h2 = load_h4(p2.x, lane);
        float4 h3 = load_h4(p3.x, lane);
        float e0 = __int_as_float(p0.y), e1 = __int_as_float(p1.y);
        float e2 = __int_as_float(p2.y), e3 = __int_as_float(p3.y);
        acc.x = fmaf(e0, h0.x, acc.x); acc.y = fmaf(e0, h0.y, acc.y);
        acc.z = fmaf(e0, h0.z, acc.z); acc.w = fmaf(e0, h0.w, acc.w);
        acc.x = fmaf(e1, h1.x, acc.x); acc.y = fmaf(e1, h1.y, acc.y);
        acc.z = fmaf(e1, h1.z, acc.z); acc.w = fmaf(e1, h1.w, acc.w);
        acc.x = fmaf(e2, h2.x, acc.x); acc.y = fmaf(e2, h2.y, acc.y);
        acc.z = fmaf(e2, h2.z, acc.z); acc.w = fmaf(e2, h2.w, acc.w);
        acc.x = fmaf(e3, h3.x, acc.x); acc.y = fmaf(e3, h3.y, acc.y);
        acc.z = fmaf(e3, h3.z, acc.z); acc.w = fmaf(e3, h3.w, acc.w);
        denom += (e0 + e1) + (e2 + e3);
    }
    for (; e < end; e++) {
        int2 p0 = g_sedge[e];
        float e0 = __int_as_float(p0.y);
        float4 h0 = load_h4(p0.x, lane);
        acc.x = fmaf(e0, h0.x, acc.x); acc.y = fmaf(e0, h0.y, acc.y);
        acc.z = fmaf(e0, h0.z, acc.z); acc.w = fmaf(e0, h0.w, acc.w);
        denom += e0;
    }
    float wgt = __fdividef(1.0f, denom + 1e-16f);
    float4 b = *(const float4*)(bias + lane * 4);
    float4 o;
    o.x = fmaf(acc.x, wgt, b.x);
    o.y = fmaf(acc.y, wgt, b.y);
    o.z = fmaf(acc.z, wgt, b.z);
    o.w = fmaf(acc.w, wgt, b.w);
    *(float4*)(out + (size_t)warp * 128 + lane * 4) = o;
}

// ---------------- launch -----------------------------------------------------
extern "C" void kernel_launch(void* const* d_in, const int* in_sizes, int n_in,
                              void* d_out, int out_size) {
    const float* x         = (const float*)d_in[0];
    const int*   ei32      = (const int*)d_in[1];
    const float* edge_attr = (const float*)d_in[2];
    const float* W         = (const float*)d_in[3];
    const float* W_edge    = (const float*)d_in[4];
    const float* att_src   = (const float*)d_in[5];
    const float* att_dst   = (const float*)d_in[6];
    const float* att_edge  = (const float*)d_in[7];
    const float* bias      = (const float*)d_in[8];
    float* out = (float*)d_out;

    int N = in_sizes[0] / 128;
    int E = in_sizes[1] / 2;
    int nblk = (N + SCAN_BLK - 1) / SCAN_BLK;

    // One-time resources, created on the first (non-capture) correctness call.
    static bool s_init = false;
    static cudaStream_t s_gemm;
    static cudaEvent_t s_evFork, s_evJoin;
    if (!s_init) {
        cudaStreamCreateWithFlags(&s_gemm, cudaStreamNonBlocking);
        cudaEventCreateWithFlags(&s_evFork, cudaEventDisableTiming);
        cudaEventCreateWithFlags(&s_evJoin, cudaEventDisableTiming);
        const int GEMM_SMEM = 128 * 64 * (int)sizeof(float2);
        cudaFuncSetAttribute(gemm_h_kernel, cudaFuncAttributeMaxDynamicSharedMemorySize, GEMM_SMEM);
        s_init = true;
    }
    const int GEMM_SMEM = 128 * 64 * (int)sizeof(float2);   // 64 KB

    // fork: gemm branch runs concurrently with index-prep branch (R6 topology)
    cudaEventRecord(s_evFork, 0);
    cudaStreamWaitEvent(s_gemm, s_evFork, 0);
    gemm_h_kernel<<<(N + 127) / 128, 256, GEMM_SMEM, s_gemm>>>(x, W, att_src, att_dst, N);
    cudaEventRecord(s_evJoin, s_gemm);

    // index-prep branch on the base stream
    init_kernel<<<160, 256>>>(W_edge, att_edge, N);
    convert_idx_kernel<<<1024, 256>>>(ei32, E, N);
    scan_phase1<<<nblk, SCAN_BLK>>>(N);
    scan_phase2<<<1, SCAN_BLK>>>(nblk);
    scan_phase3<<<nblk, SCAN_BLK>>>(N, E);

    // join: edge_pass1 needs both branches
    cudaStreamWaitEvent(0, s_evJoin, 0);
    edge_pass1<<<(E + 255) / 256, 256>>>(edge_attr, E);
    aggregate_kernel<<<(N * 32 + 255) / 256, 256>>>(bias, out, N);
}